// round 16
// baseline (speedup 1.0000x reference)
#include <cuda_runtime.h>
#include <cuda_fp16.h>

// GravityDecoder, two-phase with PDL:
//   K1: streaming fp32->fp16 convert FUSED with m[n]=dot(z[n],W)+b.
//       16 floats/thread, 8 threads/row, 4 rows per warp-iteration ->
//       0.75 shfl-instructions per row (vs 2 in R15), uint4 stores.
//   K2: frozen best shape (4 lanes/edge, 8 edges/warp, 8 LDG.128 in flight,
//       m_j gathered fp32), 5 blocks/SM.

#define MAX_N 100000
__device__ static uint4 g_zh[MAX_N * 16];   // fp16 z rows: 256 B/row
__device__ static float g_m[MAX_N];         // m = z@W + b

#define WARPS_PER_BLOCK 8
#define THREADS (WARPS_PER_BLOCK * 32)
#define K1_BLOCKS 1480

// ------------- Kernel 1: streaming convert + fused m computation -------------
// chunk c covers floats [c*16, c*16+16); row = c>>3, chunk-in-row q = c&7.
// Grid stride (K1_BLOCKS*THREADS = 378880) is a multiple of 8 -> q invariant.
__global__ __launch_bounds__(THREADS) void precompute_kernel(
    const float* __restrict__ z,
    const float* __restrict__ W,
    const float* __restrict__ b_ptr,
    int n16 /* = N*8, multiple of 32 */)
{
    const int tid     = (int)(blockIdx.x * (unsigned)blockDim.x + threadIdx.x);
    const int nthread = (int)(gridDim.x * (unsigned)blockDim.x);
    const int lane    = threadIdx.x & 31;

    const float b = *b_ptr;

    // This thread's 16 W coefficients (loop-invariant)
    const int q = tid & 7;
    const float4 w0 = reinterpret_cast<const float4*>(W)[q * 4];
    const float4 w1 = reinterpret_cast<const float4*>(W)[q * 4 + 1];
    const float4 w2 = reinterpret_cast<const float4*>(W)[q * 4 + 2];
    const float4 w3 = reinterpret_cast<const float4*>(W)[q * 4 + 3];

    uint4* __restrict__ zh4 = reinterpret_cast<uint4*>(g_zh);
    const float4* __restrict__ z4 = reinterpret_cast<const float4*>(z);

    for (int c = tid; c < n16; c += nthread) {
        const float4 v0 = z4[(size_t)c * 4];
        const float4 v1 = z4[(size_t)c * 4 + 1];
        const float4 v2 = z4[(size_t)c * 4 + 2];
        const float4 v3 = z4[(size_t)c * 4 + 3];

        // convert 16 floats -> 8 half2 -> 2 uint4 stores
        const __half2 h0 = __floats2half2_rn(v0.x, v0.y);
        const __half2 h1 = __floats2half2_rn(v0.z, v0.w);
        const __half2 h2 = __floats2half2_rn(v1.x, v1.y);
        const __half2 h3 = __floats2half2_rn(v1.z, v1.w);
        const __half2 h4 = __floats2half2_rn(v2.x, v2.y);
        const __half2 h5 = __floats2half2_rn(v2.z, v2.w);
        const __half2 h6 = __floats2half2_rn(v3.x, v3.y);
        const __half2 h7 = __floats2half2_rn(v3.z, v3.w);
        uint4 p0, p1;
        p0.x = *reinterpret_cast<const unsigned*>(&h0);
        p0.y = *reinterpret_cast<const unsigned*>(&h1);
        p0.z = *reinterpret_cast<const unsigned*>(&h2);
        p0.w = *reinterpret_cast<const unsigned*>(&h3);
        p1.x = *reinterpret_cast<const unsigned*>(&h4);
        p1.y = *reinterpret_cast<const unsigned*>(&h5);
        p1.z = *reinterpret_cast<const unsigned*>(&h6);
        p1.w = *reinterpret_cast<const unsigned*>(&h7);
        zh4[(size_t)c * 2]     = p0;
        zh4[(size_t)c * 2 + 1] = p1;

        // fused partial dot (fp32-exact)
        float part = v0.x * w0.x + v0.y * w0.y + v0.z * w0.z + v0.w * w0.w
                   + v1.x * w1.x + v1.y * w1.y + v1.z * w1.z + v1.w * w1.w
                   + v2.x * w2.x + v2.y * w2.y + v2.z * w2.z + v2.w * w2.w
                   + v3.x * w3.x + v3.y * w3.y + v3.z * w3.z + v3.w * w3.w;

        // 3-step butterfly within each 8-lane group (4 rows per warp)
        #pragma unroll
        for (int off = 4; off > 0; off >>= 1)
            part += __shfl_xor_sync(0xffffffffu, part, off);

        if ((lane & 7) == 0)
            g_m[c >> 3] = part + b;
    }
    cudaTriggerProgrammaticLaunchCompletion();
}

// ---------------- Kernel 2: per-edge distance + outputs (frozen best) ----------------
__device__ __forceinline__ float d2_accum(uint4 A, uint4 C, float acc)
{
    const unsigned* pa = &A.x;
    const unsigned* pc = &C.x;
    #pragma unroll
    for (int k = 0; k < 4; k++) {
        const __half2 ha = *reinterpret_cast<const __half2*>(&pa[k]);
        const __half2 hc = *reinterpret_cast<const __half2*>(&pc[k]);
        const __half2 d  = __hsub2(ha, hc);
        const float2  df = __half22float2(d);
        acc += df.x * df.x + df.y * df.y;
    }
    return acc;
}

__global__ __launch_bounds__(THREADS, 5) void gravity_decoder_kernel(
    const int* __restrict__ edge_index,
    float* __restrict__ out,
    int E)
{
    const int lane   = threadIdx.x & 31;
    const int sub    = lane & 3;        // sublane within 4-lane group
    const int group  = lane >> 2;       // 0..7 : which edge of the 8
    const int warp   = (int)((blockIdx.x * (unsigned)blockDim.x + threadIdx.x) >> 5);
    const int nwarps = (int)((gridDim.x * (unsigned)blockDim.x) >> 5);
    const int stride = nwarps * 8;

    float* __restrict__ out_logits = out;
    float* __restrict__ out_prob   = out + (size_t)E;
    float* __restrict__ out_mj     = out + 2 * (size_t)E;
    float* __restrict__ out_d2     = out + 3 * (size_t)E;

    int e8 = warp * 8;
    if (e8 >= E) {
        cudaGridDependencySynchronize();
        return;
    }

    // Prologue index loads (independent of K1) before the dependency sync.
    int e  = e8 + group;
    int es = (e < E) ? e : (E - 1);
    int src = __ldcs(edge_index + es);
    int dst = __ldcs(edge_index + es + (size_t)E);

    cudaGridDependencySynchronize();   // g_zh / g_m valid after this

    for (; e8 < E; e8 += stride) {
        const int  ecur  = e8 + group;
        const bool alive = (ecur < E);

        const uint4* __restrict__ zi = g_zh + (size_t)src * 16;
        const uint4* __restrict__ zj = g_zh + (size_t)dst * 16;

        // 8 gathers in flight per thread
        const uint4 A0 = zi[sub];
        const uint4 A1 = zi[sub + 4];
        const uint4 A2 = zi[sub + 8];
        const uint4 A3 = zi[sub + 12];
        const uint4 C0 = zj[sub];
        const uint4 C1 = zj[sub + 4];
        const uint4 C2 = zj[sub + 8];
        const uint4 C3 = zj[sub + 12];

        // m_j: same address across the 4-lane group -> broadcast
        const float mj = __ldg(g_m + dst);

        // Prefetch next iteration's indices while gathers are in flight
        const int e8n = e8 + stride;
        if (e8n < E) {
            const int en  = e8n + group;
            const int esn = (en < E) ? en : (E - 1);
            src = __ldcs(edge_index + esn);
            dst = __ldcs(edge_index + esn + (size_t)E);
        }

        float d2 = 0.0f;
        d2 = d2_accum(A0, C0, d2);
        d2 = d2_accum(A1, C1, d2);
        d2 = d2_accum(A2, C2, d2);
        d2 = d2_accum(A3, C3, d2);

        // 2-step butterfly within each 4-lane group
        #pragma unroll
        for (int off = 2; off > 0; off >>= 1)
            d2 += __shfl_xor_sync(0xffffffffu, d2, off);

        d2 += 1e-7f;
        const float logit = mj - __logf(d2);

        if (alive) {
            if (sub == 0)      __stcs(out_logits + ecur, logit);
            else if (sub == 1) __stcs(out_prob + ecur, __fdividef(1.0f, 1.0f + __expf(-logit)));
            else if (sub == 2) __stcs(out_mj + ecur, mj);
            else               __stcs(out_d2 + ecur, d2);
        }
    }
}

extern "C" void kernel_launch(void* const* d_in, const int* in_sizes, int n_in,
                              void* d_out, int out_size)
{
    const float* z   = (const float*)d_in[0];
    const int*   ei  = (const int*)d_in[1];
    const float* W   = (const float*)d_in[2];
    const float* b   = (const float*)d_in[3];
    float*       out = (float*)d_out;

    const int N = in_sizes[0] / 128;
    const int E = in_sizes[1] / 2;

    // K1: streaming convert + fused m (16 floats/thread)
    const int n16 = N * 8;
    precompute_kernel<<<K1_BLOCKS, THREADS>>>(z, W, b, n16);

    // K2: 8 edges per warp, PDL overlap with K1 tail
    int blocks2 = (E + WARPS_PER_BLOCK * 8 - 1) / (WARPS_PER_BLOCK * 8);
    if (blocks2 > 4736) blocks2 = 4736;

    cudaLaunchConfig_t cfg = {};
    cfg.gridDim  = dim3((unsigned)blocks2, 1, 1);
    cfg.blockDim = dim3(THREADS, 1, 1);
    cfg.dynamicSmemBytes = 0;
    cfg.stream = 0;
    cudaLaunchAttribute attrs[1];
    attrs[0].id = cudaLaunchAttributeProgrammaticStreamSerialization;
    attrs[0].val.programmaticStreamSerializationAllowed = 1;
    cfg.attrs = attrs;
    cfg.numAttrs = 1;
    cudaLaunchKernelEx(&cfg, gravity_decoder_kernel, ei, out, E);
}

// round 17
// speedup vs baseline: 1.1635x; 1.1635x over previous
#include <cuda_runtime.h>
#include <cuda_fp16.h>

// GravityDecoder, two-phase with PDL (R13 + persistent K2 grid):
//   K1: pure streaming convert z(f32) -> g_zh(f16).
//   K2: 4 lanes/edge, 8 edges/warp, 8 LDG.128 in flight; m_j recomputed from
//       the gathered z_j row (fp16 W in smem). PERSISTENT grid: 740 blocks
//       (5/SM, one wave) so each warp runs ~13 iterations and the index
//       prefetch pipeline covers nearly all of them.

#define MAX_N 100000
__device__ static uint4 g_zh[MAX_N * 16];   // fp16 z rows: 256 B/row

#define WARPS_PER_BLOCK 8
#define THREADS (WARPS_PER_BLOCK * 32)

// ---------------- Kernel 1: streaming fp32 -> fp16 convert ----------------
__global__ __launch_bounds__(THREADS) void precompute_kernel(
    const float* __restrict__ z, int n_chunks /* = N*128/8 */)
{
    const int tid     = (int)(blockIdx.x * (unsigned)blockDim.x + threadIdx.x);
    const int nthread = (int)(gridDim.x * (unsigned)blockDim.x);

    uint2* __restrict__ zh2 = reinterpret_cast<uint2*>(g_zh);
    const float4* __restrict__ z4 = reinterpret_cast<const float4*>(z);

    for (int c = tid; c < n_chunks; c += nthread) {
        const float4 v0 = z4[(size_t)c * 2];
        const float4 v1 = z4[(size_t)c * 2 + 1];
        const __half2 h0 = __floats2half2_rn(v0.x, v0.y);
        const __half2 h1 = __floats2half2_rn(v0.z, v0.w);
        const __half2 h2 = __floats2half2_rn(v1.x, v1.y);
        const __half2 h3 = __floats2half2_rn(v1.z, v1.w);
        uint2 p0, p1;
        p0.x = *reinterpret_cast<const unsigned*>(&h0);
        p0.y = *reinterpret_cast<const unsigned*>(&h1);
        p1.x = *reinterpret_cast<const unsigned*>(&h2);
        p1.y = *reinterpret_cast<const unsigned*>(&h3);
        zh2[(size_t)c * 2]     = p0;
        zh2[(size_t)c * 2 + 1] = p1;
    }
    cudaTriggerProgrammaticLaunchCompletion();
}

// ---------------- Kernel 2: per-edge distance + mj + outputs ----------------
__device__ __forceinline__ void chunk_accum(uint4 A, uint4 C, uint4 Wq,
                                            float& d2, __half2& mjacc)
{
    const unsigned* pa = &A.x;
    const unsigned* pc = &C.x;
    const unsigned* pw = &Wq.x;
    #pragma unroll
    for (int k = 0; k < 4; k++) {
        const __half2 ha = *reinterpret_cast<const __half2*>(&pa[k]);
        const __half2 hc = *reinterpret_cast<const __half2*>(&pc[k]);
        const __half2 hw = *reinterpret_cast<const __half2*>(&pw[k]);
        const __half2 d  = __hsub2(ha, hc);
        const float2  df = __half22float2(d);
        d2 += df.x * df.x + df.y * df.y;
        mjacc = __hfma2(hc, hw, mjacc);
    }
}

__global__ __launch_bounds__(THREADS, 5) void gravity_decoder_kernel(
    const int* __restrict__ edge_index,
    const float* __restrict__ W,
    const float* __restrict__ b_ptr,
    float* __restrict__ out,
    int E)
{
    // fp16 W in shared memory: 128 halves = 16 uint4 chunks of 8 coeffs.
    __shared__ uint4 s_w[16];
    if (threadIdx.x < 64) {
        const float2 w2 = reinterpret_cast<const float2*>(W)[threadIdx.x];
        const __half2 h = __floats2half2_rn(w2.x, w2.y);
        reinterpret_cast<unsigned*>(s_w)[threadIdx.x] =
            *reinterpret_cast<const unsigned*>(&h);
    }
    __syncthreads();

    const int lane   = threadIdx.x & 31;
    const int sub    = lane & 3;        // sublane within 4-lane group
    const int group  = lane >> 2;       // 0..7 : which edge of the 8
    const int warp   = (int)((blockIdx.x * (unsigned)blockDim.x + threadIdx.x) >> 5);
    const int nwarps = (int)((gridDim.x * (unsigned)blockDim.x) >> 5);
    const int stride = nwarps * 8;

    const float b = *b_ptr;

    float* __restrict__ out_logits = out;
    float* __restrict__ out_prob   = out + (size_t)E;
    float* __restrict__ out_mj     = out + 2 * (size_t)E;
    float* __restrict__ out_d2     = out + 3 * (size_t)E;

    int e8 = warp * 8;
    if (e8 >= E) {
        cudaGridDependencySynchronize();
        return;
    }

    // Prologue index loads (independent of K1) before the dependency sync.
    int e  = e8 + group;
    int es = (e < E) ? e : (E - 1);
    int src = __ldcs(edge_index + es);
    int dst = __ldcs(edge_index + es + (size_t)E);

    cudaGridDependencySynchronize();   // g_zh valid after this

    for (; e8 < E; e8 += stride) {
        const int  ecur  = e8 + group;
        const bool alive = (ecur < E);

        const uint4* __restrict__ zi = g_zh + (size_t)src * 16;
        const uint4* __restrict__ zj = g_zh + (size_t)dst * 16;

        // 8 gathers in flight per thread
        const uint4 A0 = zi[sub];
        const uint4 A1 = zi[sub + 4];
        const uint4 A2 = zi[sub + 8];
        const uint4 A3 = zi[sub + 12];
        const uint4 C0 = zj[sub];
        const uint4 C1 = zj[sub + 4];
        const uint4 C2 = zj[sub + 8];
        const uint4 C3 = zj[sub + 12];

        // Prefetch next iteration's indices while gathers are in flight
        const int e8n = e8 + stride;
        if (e8n < E) {
            const int en  = e8n + group;
            const int esn = (en < E) ? en : (E - 1);
            src = __ldcs(edge_index + esn);
            dst = __ldcs(edge_index + esn + (size_t)E);
        }

        float d2 = 0.0f;
        __half2 m0 = __floats2half2_rn(0.f, 0.f);
        __half2 m1 = m0;
        chunk_accum(A0, C0, s_w[sub],      d2, m0);
        chunk_accum(A1, C1, s_w[sub + 4],  d2, m1);
        chunk_accum(A2, C2, s_w[sub + 8],  d2, m0);
        chunk_accum(A3, C3, s_w[sub + 12], d2, m1);

        const float2 f0 = __half22float2(m0);
        const float2 f1 = __half22float2(m1);
        float mj = (f0.x + f0.y) + (f1.x + f1.y);

        // 2-step butterfly within each 4-lane group (both scalars)
        #pragma unroll
        for (int off = 2; off > 0; off >>= 1) {
            d2 += __shfl_xor_sync(0xffffffffu, d2, off);
            mj += __shfl_xor_sync(0xffffffffu, mj, off);
        }

        mj += b;
        d2 += 1e-7f;
        const float logit = mj - __logf(d2);

        if (alive) {
            if (sub == 0)      __stcs(out_logits + ecur, logit);
            else if (sub == 1) __stcs(out_prob + ecur, __fdividef(1.0f, 1.0f + __expf(-logit)));
            else if (sub == 2) __stcs(out_mj + ecur, mj);
            else               __stcs(out_d2 + ecur, d2);
        }
    }
}

extern "C" void kernel_launch(void* const* d_in, const int* in_sizes, int n_in,
                              void* d_out, int out_size)
{
    const float* z   = (const float*)d_in[0];
    const int*   ei  = (const int*)d_in[1];
    const float* W   = (const float*)d_in[2];
    const float* b   = (const float*)d_in[3];
    float*       out = (float*)d_out;

    const int N = in_sizes[0] / 128;
    const int E = in_sizes[1] / 2;

    // K1: streaming convert, persistent grid
    const int n_chunks = N * 16;
    precompute_kernel<<<1480, THREADS>>>(z, n_chunks);

    // K2: PERSISTENT grid — one full-residency wave (5 blocks/SM x 148 SMs),
    // each warp runs ~13 grid-stride iterations so the index prefetch
    // pipeline is effective nearly everywhere.
    int blocks2 = 5 * 148;   // 740
    {
        int needed = (E + WARPS_PER_BLOCK * 8 - 1) / (WARPS_PER_BLOCK * 8);
        if (blocks2 > needed) blocks2 = needed;
    }

    cudaLaunchConfig_t cfg = {};
    cfg.gridDim  = dim3((unsigned)blocks2, 1, 1);
    cfg.blockDim = dim3(THREADS, 1, 1);
    cfg.dynamicSmemBytes = 0;
    cfg.stream = 0;
    cudaLaunchAttribute attrs[1];
    attrs[0].id = cudaLaunchAttributeProgrammaticStreamSerialization;
    attrs[0].val.programmaticStreamSerializationAllowed = 1;
    cfg.attrs = attrs;
    cfg.numAttrs = 1;
    cudaLaunchKernelEx(&cfg, gravity_decoder_kernel, ei, W, b, out, E);
}